// round 11
// baseline (speedup 1.0000x reference)
#include <cuda_runtime.h>
#include <math.h>

#define N_RAYS   4096
#define N_SAMP   192
#define S_TOTAL  (N_RAYS * N_SAMP)   // 786432
#define TILE_M   128
#define A_W      135                  // 0-127 act | 128-130 pos | 131-133 view | 134 pad (odd width: no bank conflict on strided row loads)
#define NT       256

// smem: A tile + weight staging (max 131x128) + bias staging (128)
#define SMEM_FLOATS (TILE_M * A_W + 131 * 128 + 128)
#define SMEM_BYTES  (SMEM_FLOATS * 4)

__device__ __forceinline__ void copyw(float* dst, const float* __restrict__ src, int n) {
    const float4* s4 = (const float4*)src;
    float4* d4 = (float4*)dst;
    int n4 = n >> 2;
    for (int i = threadIdx.x; i < n4; i += NT) d4[i] = s4[i];
}
__device__ __forceinline__ void copyb(float* dst, const float* __restrict__ src, int n) {
    for (int i = threadIdx.x; i < n; i += NT) dst[i] = src[i];
}

// GEMM: [128 rows x K] @ [K x 128] + bias, ReLU, writeback into A cols 0..127.
// a_base: column offset in A where the K inputs start (128 for layer0 reading pos).
// skip:   added to A-column index for k>=128 (r-layer gathers view at cols 131-133).
__device__ __forceinline__ void dense128(float* A, const float* Wt, const float* Bs,
                                         int K, int a_base, int skip) {
    const int tx = threadIdx.x & 15;   // 16 col-groups of 8
    const int ty = threadIdx.x >> 4;   // 16 row-groups; rows ty + 16*j
    float acc[8][8];
#pragma unroll
    for (int i = 0; i < 8; i++) {
        float bv = Bs[tx * 8 + i];
#pragma unroll
        for (int j = 0; j < 8; j++) acc[j][i] = bv;
    }
#pragma unroll 4
    for (int k = 0; k < K; k++) {
        int ka = a_base + k + ((k >= 128) ? skip : 0);
        float a[8];
#pragma unroll
        for (int j = 0; j < 8; j++) a[j] = A[(ty + 16 * j) * A_W + ka];
        float4 b0v = *(const float4*)&Wt[k * 128 + tx * 8];
        float4 b1v = *(const float4*)&Wt[k * 128 + tx * 8 + 4];
        float b[8] = {b0v.x, b0v.y, b0v.z, b0v.w, b1v.x, b1v.y, b1v.z, b1v.w};
#pragma unroll
        for (int j = 0; j < 8; j++)
#pragma unroll
            for (int i = 0; i < 8; i++)
                acc[j][i] = fmaf(a[j], b[i], acc[j][i]);
    }
    __syncthreads();   // all reads of A / Wt done before overwrite
#pragma unroll
    for (int j = 0; j < 8; j++)
#pragma unroll
        for (int i = 0; i < 8; i++)
            A[(ty + 16 * j) * A_W + tx * 8 + i] = fmaxf(acc[j][i], 0.f);
    __syncthreads();
}

// r-layer: [128 x 131] @ [131 x 64] + br, ReLU -> A cols 0..63.
// Inputs: features at A cols 0..127, view at cols 131..133.
__device__ __forceinline__ void dense_r(float* A, const float* Wt, const float* Bs) {
    const int tx = threadIdx.x & 7;    // 8 col-groups of 8 (N=64)
    const int ty = threadIdx.x >> 3;   // 32 row-groups; rows ty + 32*j
    float acc[4][8];
#pragma unroll
    for (int i = 0; i < 8; i++) {
        float bv = Bs[tx * 8 + i];
#pragma unroll
        for (int j = 0; j < 4; j++) acc[j][i] = bv;
    }
#pragma unroll 4
    for (int k = 0; k < 131; k++) {
        int ka = (k < 128) ? k : k + 3;
        float a[4];
#pragma unroll
        for (int j = 0; j < 4; j++) a[j] = A[(ty + 32 * j) * A_W + ka];
        float4 b0v = *(const float4*)&Wt[k * 64 + tx * 8];
        float4 b1v = *(const float4*)&Wt[k * 64 + tx * 8 + 4];
        float b[8] = {b0v.x, b0v.y, b0v.z, b0v.w, b1v.x, b1v.y, b1v.z, b1v.w};
#pragma unroll
        for (int j = 0; j < 4; j++)
#pragma unroll
            for (int i = 0; i < 8; i++)
                acc[j][i] = fmaf(a[j], b[i], acc[j][i]);
    }
    __syncthreads();
#pragma unroll
    for (int j = 0; j < 4; j++)
#pragma unroll
        for (int i = 0; i < 8; i++)
            A[(ty + 32 * j) * A_W + tx * 8 + i] = fmaxf(acc[j][i], 0.f);
    __syncthreads();
}

__global__ void __launch_bounds__(NT, 1) nerf_fused_kernel(
    const float* __restrict__ x,
    const float* __restrict__ w0, const float* __restrict__ b0,
    const float* __restrict__ w1, const float* __restrict__ b1,
    const float* __restrict__ w2, const float* __restrict__ b2,
    const float* __restrict__ w3, const float* __restrict__ b3,
    const float* __restrict__ wd, const float* __restrict__ bd,
    const float* __restrict__ wf, const float* __restrict__ bf,
    const float* __restrict__ wr, const float* __restrict__ br,
    const float* __restrict__ wo, const float* __restrict__ bo,
    float* __restrict__ out) {
    extern __shared__ float smem[];
    float* A  = smem;                    // TILE_M * A_W
    float* Wt = A + TILE_M * A_W;        // up to 131*128
    float* Bs = Wt + 131 * 128;          // 128

    const int tid = threadIdx.x;
    const int s0 = blockIdx.x * TILE_M;

    // Stage x tile: pos -> cols 128..130, view -> cols 131..133
    for (int i = tid; i < TILE_M * 6; i += NT) {
        int r = i / 6, c = i % 6;
        A[r * A_W + 128 + c] = x[(size_t)(s0 + r) * 6 + c];
    }
    __syncthreads();

    // Layer 0: pos(3) -> 128
    copyw(Wt, w0, 3 * 128);  copyb(Bs, b0, 128);
    __syncthreads();
    dense128(A, Wt, Bs, 3, 128, 0);

    // Layer 1: 128 -> 128
    copyw(Wt, w1, 128 * 128); copyb(Bs, b1, 128);
    __syncthreads();
    dense128(A, Wt, Bs, 128, 0, 0);

    // Layer 2: [h, pos](131) -> 128  (pos contiguous at cols 128..130)
    copyw(Wt, w2, 131 * 128); copyb(Bs, b2, 128);
    __syncthreads();
    dense128(A, Wt, Bs, 131, 0, 0);

    // Layer 3: 128 -> 128
    copyw(Wt, w3, 128 * 128); copyb(Bs, b3, 128);
    __syncthreads();
    dense128(A, Wt, Bs, 128, 0, 0);

    // Stage wf (features) and wd (density head) together; bf -> Bs
    copyw(Wt, wf, 128 * 128);
    copyw(Wt + 128 * 128, wd, 128);
    copyb(Bs, bf, 128);
    __syncthreads();

    // Density: relu(h3 @ wd + bd), one row per thread (tid < 128), BEFORE A is overwritten
    if (tid < TILE_M) {
        const float* wds = Wt + 128 * 128;
        float d = bd[0];
#pragma unroll 8
        for (int k = 0; k < 128; k++) d = fmaf(A[tid * A_W + k], wds[k], d);
        out[3 * S_TOTAL + s0 + tid] = fmaxf(d, 0.f);
    }
    // Features: relu(h3 @ wf + bf) -> A cols 0..127 (internal sync orders density reads before writeback)
    dense128(A, Wt, Bs, 128, 0, 0);

    // r-layer: [features, view](131) -> 64
    copyw(Wt, wr, 131 * 64); copyb(Bs, br, 64);
    __syncthreads();
    dense_r(A, Wt, Bs);

    // Output layer: sigmoid(r @ wo + bo), 3 cols; one row per thread
    copyw(Wt, wo, 64 * 3); copyb(Bs, bo, 3);
    __syncthreads();
    if (tid < TILE_M) {
        float s0v = Bs[0], s1v = Bs[1], s2v = Bs[2];
#pragma unroll 8
        for (int k = 0; k < 64; k++) {
            float av = A[tid * A_W + k];
            s0v = fmaf(av, Wt[k * 3 + 0], s0v);
            s1v = fmaf(av, Wt[k * 3 + 1], s1v);
            s2v = fmaf(av, Wt[k * 3 + 2], s2v);
        }
        size_t o = (size_t)(s0 + tid) * 3;
        out[o + 0] = 1.f / (1.f + expf(-s0v));
        out[o + 1] = 1.f / (1.f + expf(-s1v));
        out[o + 2] = 1.f / (1.f + expf(-s2v));
    }
}

extern "C" void kernel_launch(void* const* d_in, const int* in_sizes, int n_in,
                              void* d_out, int out_size) {
    (void)in_sizes; (void)n_in; (void)out_size;
    const float* x  = (const float*)d_in[0];
    const float* w0 = (const float*)d_in[1];  const float* b0 = (const float*)d_in[2];
    const float* w1 = (const float*)d_in[3];  const float* b1 = (const float*)d_in[4];
    const float* w2 = (const float*)d_in[5];  const float* b2 = (const float*)d_in[6];
    const float* w3 = (const float*)d_in[7];  const float* b3 = (const float*)d_in[8];
    const float* wd = (const float*)d_in[9];  const float* bd = (const float*)d_in[10];
    const float* wf = (const float*)d_in[11]; const float* bf = (const float*)d_in[12];
    const float* wr = (const float*)d_in[13]; const float* br = (const float*)d_in[14];
    const float* wo = (const float*)d_in[15]; const float* bo = (const float*)d_in[16];
    float* out = (float*)d_out;

    cudaFuncSetAttribute(nerf_fused_kernel,
                         cudaFuncAttributeMaxDynamicSharedMemorySize, SMEM_BYTES);
    nerf_fused_kernel<<<S_TOTAL / TILE_M, NT, SMEM_BYTES>>>(
        x, w0, b0, w1, b1, w2, b2, w3, b3, wd, bd, wf, bf, wr, br, wo, bo, out);
}

// round 13
// speedup vs baseline: 9.7113x; 9.7113x over previous
#include <cuda_runtime.h>
#include <cuda_fp16.h>
#include <cstdint>
#include <math.h>

#define N_RAYS   4096
#define N_SAMP   192
#define S_TOTAL  (N_RAYS * N_SAMP)   // 786432
#define TILE_M   256
#define NT       256

// ---------------------------------------------------------------------------
// helpers
// ---------------------------------------------------------------------------
__device__ __forceinline__ uint32_t smem_u32(const void* p) {
    uint32_t a;
    asm("{ .reg .u64 t; cvta.to.shared.u64 t, %1; cvt.u32.u64 %0, t; }" : "=r"(a) : "l"(p));
    return a;
}

__device__ __forceinline__ void ldsm_x4(uint32_t* r, uint32_t addr) {
    asm volatile("ldmatrix.sync.aligned.m8n8.x4.shared.b16 {%0,%1,%2,%3}, [%4];"
        : "=r"(r[0]), "=r"(r[1]), "=r"(r[2]), "=r"(r[3]) : "r"(addr));
}

__device__ __forceinline__ void mma16816(float* c, const uint32_t* a, const uint32_t* b) {
    asm volatile("mma.sync.aligned.m16n8k16.row.col.f32.f16.f16.f32 "
        "{%0,%1,%2,%3}, {%4,%5,%6,%7}, {%8,%9}, {%0,%1,%2,%3};"
        : "+f"(c[0]), "+f"(c[1]), "+f"(c[2]), "+f"(c[3])
        : "r"(a[0]), "r"(a[1]), "r"(a[2]), "r"(a[3]), "r"(b[0]), "r"(b[1]));
}

#define CP_ASYNC16(dst, src) \
    asm volatile("cp.async.cg.shared.global [%0], [%1], 16;" :: "r"(dst), "l"(src) : "memory")
#define CP_COMMIT()  asm volatile("cp.async.commit_group;" ::: "memory")
#define CP_WAIT0()   asm volatile("cp.async.wait_group 0;" ::: "memory")

// ---------------------------------------------------------------------------
// Prepared weights: fp16, B^T layout: Bt[n][k] = W[k][n], row = 256B,
// k-chunk (16B) XOR-swizzled by (n&7) for conflict-free ldmatrix.
// One contiguous buffer: W1 | W2 | W3 | WF | WR (ushort offsets below)
// ---------------------------------------------------------------------------
#define GW_W1 0
#define GW_W2 16384
#define GW_W3 32768
#define GW_WF 49152
#define GW_WR 65536
__device__ __align__(16) unsigned short g_BW[73728];

__device__ __forceinline__ uint32_t bt_off(int n, int k) {   // byte offset
    return (uint32_t)(n * 256) + (uint32_t)(((((k >> 3) ^ (n & 7))) << 4) + ((k & 7) << 1));
}

__global__ void prep_weights(const float* __restrict__ w1, const float* __restrict__ w2,
                             const float* __restrict__ w3, const float* __restrict__ wf,
                             const float* __restrict__ wr) {
    int e = blockIdx.x * blockDim.x + threadIdx.x;
    if (e < 65536) {
        int m = e >> 14, r = e & 16383;
        int k = r >> 7, n = r & 127;
        const float* W = (m == 0) ? w1 : (m == 1) ? w2 : (m == 2) ? w3 : wf;
        g_BW[m * 16384 + (bt_off(n, k) >> 1)] = __half_as_ushort(__float2half_rn(W[k * 128 + n]));
    } else if (e < 73728) {
        int r = e - 65536;
        int k = r >> 6, n = r & 63;
        g_BW[GW_WR + (bt_off(n, k) >> 1)] = __half_as_ushort(__float2half_rn(wr[k * 64 + n]));
    }
}

// ---------------------------------------------------------------------------
// smem layout
// ---------------------------------------------------------------------------
#define OFF_F      16
#define OFF_W1     16384
#define SMEM_TOTAL (16384 + 147456)    // 160 KB

// float-region indices (relative to F)
#define FB0   0
#define FB1   128
#define FB2   256
#define FB3   384
#define FBF   512
#define FBR   640
#define FW0   704     // [3][128]
#define FW2B  1088    // [3][128]
#define FWRB  1472    // [3][64]
#define FWD   1664    // [128]
#define FWO   1792    // [64][3]
#define FBD   1984
#define FBO   1985    // 3
#define FPOS  1988    // [3][256]
#define FVIEW 2756    // [3][256]

// ---------------------------------------------------------------------------
// Generic fused layer: act(regs) @ Bt(smem) + bias (+3-wide concat), ReLU,
// repack to A-fragments. NP = N/16 (8 or 4). K fixed = 128 (8 k-tiles).
// ---------------------------------------------------------------------------
template <int NP, bool CONCAT>
__device__ __forceinline__ void run_layer(
    const uint32_t (&A)[2][8][4], uint32_t (&An)[2][8][4],
    uint32_t wsm, const float* __restrict__ Fb,
    const float* __restrict__ Fc, const float (&pr)[2][2][3], int lane)
{
    const int g  = lane >> 3, ln = lane & 7;
    const int nl = ((g >> 1) << 3) + ln;   // n offset within 16-wide pair
    const int gk = g & 1;                  // k-chunk select (lo/hi 8)
    const int cb = 2 * (lane & 3);
    constexpr int NW = NP * 16;
#pragma unroll
    for (int np = 0; np < NP; np++) {
        const int n_abs = np * 16 + nl;
        const uint32_t rowb = wsm + ((uint32_t)n_abs << 8);
        const int sw = n_abs & 7;
        uint32_t B[8][4];
#pragma unroll
        for (int kt = 0; kt < 8; kt++)
            ldsm_x4(B[kt], rowb + (uint32_t)((((kt << 1) + gk) ^ sw) << 4));
        const int n0 = np * 16 + cb, n1 = n0 + 8;
#pragma unroll
        for (int mt = 0; mt < 2; mt++) {
            float ae[4], ao[4];
            {
                float be0 = Fb[n0], be1 = Fb[n0 + 1], bq0 = Fb[n1], bq1 = Fb[n1 + 1];
                if constexpr (CONCAT) {
                    ae[0] = be0 + pr[mt][0][0]*Fc[n0]   + pr[mt][0][1]*Fc[NW+n0]   + pr[mt][0][2]*Fc[2*NW+n0];
                    ae[1] = be1 + pr[mt][0][0]*Fc[n0+1] + pr[mt][0][1]*Fc[NW+n0+1] + pr[mt][0][2]*Fc[2*NW+n0+1];
                    ae[2] = be0 + pr[mt][1][0]*Fc[n0]   + pr[mt][1][1]*Fc[NW+n0]   + pr[mt][1][2]*Fc[2*NW+n0];
                    ae[3] = be1 + pr[mt][1][0]*Fc[n0+1] + pr[mt][1][1]*Fc[NW+n0+1] + pr[mt][1][2]*Fc[2*NW+n0+1];
                    ao[0] = bq0 + pr[mt][0][0]*Fc[n1]   + pr[mt][0][1]*Fc[NW+n1]   + pr[mt][0][2]*Fc[2*NW+n1];
                    ao[1] = bq1 + pr[mt][0][0]*Fc[n1+1] + pr[mt][0][1]*Fc[NW+n1+1] + pr[mt][0][2]*Fc[2*NW+n1+1];
                    ao[2] = bq0 + pr[mt][1][0]*Fc[n1]   + pr[mt][1][1]*Fc[NW+n1]   + pr[mt][1][2]*Fc[2*NW+n1];
                    ao[3] = bq1 + pr[mt][1][0]*Fc[n1+1] + pr[mt][1][1]*Fc[NW+n1+1] + pr[mt][1][2]*Fc[2*NW+n1+1];
                } else {
                    ae[0] = be0; ae[1] = be1; ae[2] = be0; ae[3] = be1;
                    ao[0] = bq0; ao[1] = bq1; ao[2] = bq0; ao[3] = bq1;
                }
            }
#pragma unroll
            for (int kt = 0; kt < 8; kt++) {
                mma16816(ae, A[mt][kt], &B[kt][0]);
                mma16816(ao, A[mt][kt], &B[kt][2]);
            }
            __half2 h;
            h = __floats2half2_rn(fmaxf(ae[0], 0.f), fmaxf(ae[1], 0.f)); An[mt][np][0] = *(uint32_t*)&h;
            h = __floats2half2_rn(fmaxf(ae[2], 0.f), fmaxf(ae[3], 0.f)); An[mt][np][1] = *(uint32_t*)&h;
            h = __floats2half2_rn(fmaxf(ao[0], 0.f), fmaxf(ao[1], 0.f)); An[mt][np][2] = *(uint32_t*)&h;
            h = __floats2half2_rn(fmaxf(ao[2], 0.f), fmaxf(ao[3], 0.f)); An[mt][np][3] = *(uint32_t*)&h;
        }
    }
}

// ---------------------------------------------------------------------------
// main kernel
// ---------------------------------------------------------------------------
__global__ void __launch_bounds__(NT, 1) nerf_hmma_kernel(
    const float* __restrict__ x,
    const float* __restrict__ w0, const float* __restrict__ b0,
    const float* __restrict__ b1, const float* __restrict__ b2,
    const float* __restrict__ b3, const float* __restrict__ bd,
    const float* __restrict__ bf, const float* __restrict__ br,
    const float* __restrict__ bo, const float* __restrict__ w2,
    const float* __restrict__ wr, const float* __restrict__ wd,
    const float* __restrict__ wo, float* __restrict__ out)
{
    extern __shared__ char smem[];
    const uint32_t sb = smem_u32(smem);
    float* F = (float*)(smem + OFF_F);

    const int tid = threadIdx.x;
    const int w = tid >> 5, lane = tid & 31;
    const int q = lane >> 2;               // row-in-8 for this quad
    const int s0 = blockIdx.x * TILE_M;

    // ---- kick off async weight staging (fp16 prepped, contiguous 144KB) ----
    {
        uint64_t gw;
        asm("cvta.to.global.u64 %0, %1;" : "=l"(gw) : "l"((const void*)g_BW));
        for (int i = tid * 16; i < 147456; i += NT * 16)
            CP_ASYNC16(sb + OFF_W1 + (uint32_t)i, gw + (uint64_t)i);
        CP_COMMIT();
    }

    // ---- stage misc fp32 params + inputs ----
    for (int i = tid; i < 128; i += NT) {
        F[FB0 + i] = b0[i]; F[FB1 + i] = b1[i]; F[FB2 + i] = b2[i];
        F[FB3 + i] = b3[i]; F[FBF + i] = bf[i]; F[FWD + i] = wd[i];
    }
    for (int i = tid; i < 64; i += NT) F[FBR + i] = br[i];
    for (int i = tid; i < 384; i += NT) { F[FW0 + i] = w0[i]; F[FW2B + i] = w2[128 * 128 + i]; }
    for (int i = tid; i < 192; i += NT) { F[FWRB + i] = wr[128 * 64 + i]; F[FWO + i] = wo[i]; }
    if (tid == 0) { F[FBD] = bd[0]; F[FBO] = bo[0]; F[FBO + 1] = bo[1]; F[FBO + 2] = bo[2]; }
    for (int i = tid; i < TILE_M * 6; i += NT) {
        int r = i / 6, c = i % 6;
        float v = x[(size_t)(s0 + r) * 6 + c];
        if (c < 3) F[FPOS + c * 256 + r] = v; else F[FVIEW + (c - 3) * 256 + r] = v;
    }
    __syncthreads();

    uint32_t A0[2][8][4], A1[2][8][4];

    // ---- Layer 0 (K=3) via FFMA directly into A fragments ----
    {
        float px[2][2], py[2][2], pz[2][2];
#pragma unroll
        for (int mt = 0; mt < 2; mt++)
#pragma unroll
            for (int hf = 0; hf < 2; hf++) {
                int r = w * 32 + mt * 16 + hf * 8 + q;
                px[mt][hf] = F[FPOS + r]; py[mt][hf] = F[FPOS + 256 + r]; pz[mt][hf] = F[FPOS + 512 + r];
            }
        const int cbase = 2 * (lane & 3);
#pragma unroll
        for (int kt = 0; kt < 8; kt++) {
            float Bv[4], Wx[4], Wy[4], Wz[4];
#pragma unroll
            for (int j = 0; j < 4; j++) {
                int c = kt * 16 + cbase + (j >> 1) * 8 + (j & 1);
                Bv[j] = F[FB0 + c]; Wx[j] = F[FW0 + c]; Wy[j] = F[FW0 + 128 + c]; Wz[j] = F[FW0 + 256 + c];
            }
#pragma unroll
            for (int mt = 0; mt < 2; mt++)
#pragma unroll
                for (int hf = 0; hf < 2; hf++) {
                    float v0 = fmaxf(Bv[0] + px[mt][hf]*Wx[0] + py[mt][hf]*Wy[0] + pz[mt][hf]*Wz[0], 0.f);
                    float v1 = fmaxf(Bv[1] + px[mt][hf]*Wx[1] + py[mt][hf]*Wy[1] + pz[mt][hf]*Wz[1], 0.f);
                    float v8 = fmaxf(Bv[2] + px[mt][hf]*Wx[2] + py[mt][hf]*Wy[2] + pz[mt][hf]*Wz[2], 0.f);
                    float v9 = fmaxf(Bv[3] + px[mt][hf]*Wx[3] + py[mt][hf]*Wy[3] + pz[mt][hf]*Wz[3], 0.f);
                    __half2 lo = __floats2half2_rn(v0, v1), hi = __floats2half2_rn(v8, v9);
                    A0[mt][kt][hf]     = *(uint32_t*)&lo;
                    A0[mt][kt][2 + hf] = *(uint32_t*)&hi;
                }
        }
    }

    // ---- weights ready? ----
    CP_WAIT0();
    __syncthreads();

    float posr[2][2][3], viewr[2][2][3];
#pragma unroll
    for (int mt = 0; mt < 2; mt++)
#pragma unroll
        for (int hf = 0; hf < 2; hf++) {
            int r = w * 32 + mt * 16 + hf * 8 + q;
            posr[mt][hf][0] = F[FPOS + r];        posr[mt][hf][1] = F[FPOS + 256 + r];
            posr[mt][hf][2] = F[FPOS + 512 + r];
            viewr[mt][hf][0] = F[FVIEW + r];      viewr[mt][hf][1] = F[FVIEW + 256 + r];
            viewr[mt][hf][2] = F[FVIEW + 512 + r];
        }

    // ---- mainloop: NO __syncthreads, activations stay in registers ----
    run_layer<8, false>(A0, A1, sb + OFF_W1,               F + FB1, F, posr, lane);          // h1
    run_layer<8, true >(A1, A0, sb + OFF_W1 + GW_W2 * 2,   F + FB2, F + FW2B, posr, lane);   // h2 (+pos)
    run_layer<8, false>(A0, A1, sb + OFF_W1 + GW_W3 * 2,   F + FB3, F, posr, lane);          // h3

    // ---- density head from h3 (A1) ----
    {
        const float bdv = F[FBD];
        const int cbase = 2 * (lane & 3);
#pragma unroll
        for (int mt = 0; mt < 2; mt++) {
            float d0 = 0.f, d1 = 0.f;
#pragma unroll
            for (int kt = 0; kt < 8; kt++) {
                int k0 = kt * 16 + cbase;
                float2 wlo = *(const float2*)&F[FWD + k0];
                float2 whi = *(const float2*)&F[FWD + k0 + 8];
                float2 f0 = __half22float2(*(__half2*)&A1[mt][kt][0]);
                float2 f1 = __half22float2(*(__half2*)&A1[mt][kt][1]);
                float2 f2 = __half22float2(*(__half2*)&A1[mt][kt][2]);
                float2 f3 = __half22float2(*(__half2*)&A1[mt][kt][3]);
                d0 += f0.x * wlo.x + f0.y * wlo.y + f2.x * whi.x + f2.y * whi.y;
                d1 += f1.x * wlo.x + f1.y * wlo.y + f3.x * whi.x + f3.y * whi.y;
            }
            d0 += __shfl_xor_sync(0xffffffffu, d0, 1); d0 += __shfl_xor_sync(0xffffffffu, d0, 2);
            d1 += __shfl_xor_sync(0xffffffffu, d1, 1); d1 += __shfl_xor_sync(0xffffffffu, d1, 2);
            if ((lane & 3) == 0) {
                int Ra = s0 + w * 32 + mt * 16 + q;
                out[3 * S_TOTAL + Ra]     = fmaxf(d0 + bdv, 0.f);
                out[3 * S_TOTAL + Ra + 8] = fmaxf(d1 + bdv, 0.f);
            }
        }
    }

    run_layer<8, false>(A1, A0, sb + OFF_W1 + GW_WF * 2,   F + FBF, F, posr, lane);          // features
    run_layer<4, true >(A0, A1, sb + OFF_W1 + GW_WR * 2,   F + FBR, F + FWRB, viewr, lane);  // r (+view)

    // ---- rgb head from r (A1, k-tiles 0..3) ----
    {
        const int cbase = 2 * (lane & 3);
#pragma unroll
        for (int mt = 0; mt < 2; mt++) {
            float s[2][3] = {{0.f,0.f,0.f},{0.f,0.f,0.f}};
#pragma unroll
            for (int kt = 0; kt < 4; kt++) {
                int k0 = kt * 16 + cbase, k8 = k0 + 8;
                float2 f0 = __half22float2(*(__half2*)&A1[mt][kt][0]);
                float2 f1 = __half22float2(*(__half2*)&A1[mt][kt][1]);
                float2 f2 = __half22float2(*(__half2*)&A1[mt][kt][2]);
                float2 f3 = __half22float2(*(__half2*)&A1[mt][kt][3]);
#pragma unroll
                for (int c = 0; c < 3; c++) {
                    float w00 = F[FWO + k0 * 3 + c],       w01 = F[FWO + (k0 + 1) * 3 + c];
                    float w08 = F[FWO + k8 * 3 + c],       w09 = F[FWO + (k8 + 1) * 3 + c];
                    s[0][c] += f0.x * w00 + f0.y * w01 + f2.x * w08 + f2.y * w09;
                    s[1][c] += f1.x * w00 + f1.y * w01 + f3.x * w08 + f3.y * w09;
                }
            }
#pragma unroll
            for (int hf = 0; hf < 2; hf++)
#pragma unroll
                for (int c = 0; c < 3; c++) {
                    s[hf][c] += __shfl_xor_sync(0xffffffffu, s[hf][c], 1);
                    s[hf][c] += __shfl_xor_sync(0xffffffffu, s[hf][c], 2);
                }
            if ((lane & 3) == 0) {
                int Ra = s0 + w * 32 + mt * 16 + q;
#pragma unroll
                for (int hf = 0; hf < 2; hf++) {
                    size_t o = (size_t)(Ra + hf * 8) * 3;
                    out[o + 0] = 1.f / (1.f + expf(-(s[hf][0] + F[FBO])));
                    out[o + 1] = 1.f / (1.f + expf(-(s[hf][1] + F[FBO + 1])));
                    out[o + 2] = 1.f / (1.f + expf(-(s[hf][2] + F[FBO + 2])));
                }
            }
        }
    }
}

extern "C" void kernel_launch(void* const* d_in, const int* in_sizes, int n_in,
                              void* d_out, int out_size) {
    (void)in_sizes; (void)n_in; (void)out_size;
    const float* x  = (const float*)d_in[0];
    const float* w0 = (const float*)d_in[1];  const float* b0 = (const float*)d_in[2];
    const float* w1 = (const float*)d_in[3];  const float* b1 = (const float*)d_in[4];
    const float* w2 = (const float*)d_in[5];  const float* b2 = (const float*)d_in[6];
    const float* w3 = (const float*)d_in[7];  const float* b3 = (const float*)d_in[8];
    const float* wd = (const float*)d_in[9];  const float* bd = (const float*)d_in[10];
    const float* wf = (const float*)d_in[11]; const float* bf = (const float*)d_in[12];
    const float* wr = (const float*)d_in[13]; const float* br = (const float*)d_in[14];
    const float* wo = (const float*)d_in[15]; const float* bo = (const float*)d_in[16];
    float* out = (float*)d_out;

    prep_weights<<<288, 256>>>(w1, w2, w3, wf, wr);

    cudaFuncSetAttribute(nerf_hmma_kernel,
                         cudaFuncAttributeMaxDynamicSharedMemorySize, SMEM_TOTAL);
    nerf_hmma_kernel<<<S_TOTAL / TILE_M, NT, SMEM_TOTAL>>>(
        x, w0, b0, b1, b2, b3, bd, bf, br, bo, w2, wr, wd, wo, out);
}